// round 4
// baseline (speedup 1.0000x reference)
#include <cuda_runtime.h>
#include <cuda_bf16.h>
#include <cstdint>

// ---------------------------------------------------------------------------
// SE3Convolution: build [52,52,5,5,5] filter from weights+bases, then
// dense 3D VALID conv  x[8,52,48,48,48] -> out[8,52,44,44,44]
// fp32 path using packed fma.rn.f32x2 (FFMA2) for 2x FMA-pipe FLOPs.
// Staging via cp.async (LDGSTS) to cut issue cost + latency exposure.
// ---------------------------------------------------------------------------

#define NCH   52
#define DIN   48
#define DOUT  44
#define SS    5
#define TAPS  125          // 5*5*5
#define KB    4            // basis kernels per pair

#define CPG   13           // co per ty-group (6 packed pairs + 1 scalar)
#define NPY   4            // y points per thread
#define WPAD  64           // padded co-slots per tap: 4 groups x 16 floats

// Filter scratch in [ci][tap][WPAD] layout:
//   slot = (co/13)*16 + (co%13); slots 13..15 of each group zero-padded.
// Each ty-group's 13 weights per tap are a contiguous 16B-aligned run:
// 12 of them load as 3x ld.shared.v2.u64 (pre-paired for FFMA2), 1 scalar.
__device__ __align__(16) float g_kernel[NCH * TAPS * WPAD];

// packed fp32x2 fma: acc = w * v + acc  (lanewise on 2 floats in a b64 reg)
#define FMA2(acc, w, v) \
    asm("fma.rn.f32x2 %0, %1, %2, %0;" : "+l"(acc) : "l"(w), "l"(v))

// 16B global->shared async copy (LDGSTS)
#define CP_ASYNC16(dst_u32, src_ptr) \
    asm volatile("cp.async.cg.shared.global [%0], [%1], 16;" \
                 :: "r"(dst_u32), "l"(src_ptr))

// ---------------------------------------------------------------------------
// Step 1: filter construction (one thread per [ci][tap][slot] element).
// kernel[co, ci, tap] = sum_k weight[woff(i,j) + (u*m_in+v)*K + k]
//                              * basis_ij[k, a, b, tap]
// ---------------------------------------------------------------------------
__global__ void build_filter_kernel(
    const float* __restrict__ w,
    const float* __restrict__ b00, const float* __restrict__ b01, const float* __restrict__ b02,
    const float* __restrict__ b10, const float* __restrict__ b11, const float* __restrict__ b12,
    const float* __restrict__ b20, const float* __restrict__ b21, const float* __restrict__ b22)
{
    int idx = blockIdx.x * blockDim.x + threadIdx.x;
    if (idx >= NCH * TAPS * WPAD) return;

    int slot = idx % WPAD;
    int tap  = (idx / WPAD) % TAPS;
    int ci   = idx / (WPAD * TAPS);

    int grp = slot >> 4, lane = slot & 15;
    if (lane >= CPG) {                 // zero the pad slots
        g_kernel[idx] = 0.f;
        return;
    }
    int co = grp * CPG + lane;         // 0..51

    // irrep decomposition: [0,8) l=0 (d=1,m=8); [8,32) l=1 (d=3,m=8); [32,52) l=2 (d=5,m=4)
    int i, ro;
    if      (co < 8)  { i = 0; ro = 0;  }
    else if (co < 32) { i = 1; ro = 8;  }
    else              { i = 2; ro = 32; }
    int j, rc;
    if      (ci < 8)  { j = 0; rc = 0;  }
    else if (ci < 32) { j = 1; rc = 8;  }
    else              { j = 2; rc = 32; }

    const int dims[3]  = {1, 3, 5};
    const int mults[3] = {8, 8, 4};
    // weight block offsets matching the python loop order (i outer, j inner)
    const int woff[3][3] = {{0, 256, 512}, {640, 896, 1152}, {1280, 1408, 1536}};

    int d_o = dims[i], d_i = dims[j], m_i = mults[j];
    int u = (co - ro) / d_o, a = (co - ro) % d_o;
    int v = (ci - rc) / d_i, b = (ci - rc) % d_i;

    const float* B[9] = {b00, b01, b02, b10, b11, b12, b20, b21, b22};
    const float* bs = B[i * 3 + j];
    const float* wp = w + woff[i][j] + (u * m_i + v) * KB;

    float s = 0.f;
    #pragma unroll
    for (int k = 0; k < KB; k++)
        s += wp[k] * bs[((k * d_o + a) * d_i + b) * TAPS + tap];

    g_kernel[idx] = s;
}

// ---------------------------------------------------------------------------
// Step 2: direct 3D conv, fp32x2 packed FMA.
//
// Block (44,4) = 176 threads. tx = output x (44+4 = 48 = full input row).
// ty = co-group of 13. Thread: 13 co x 4 y = 52 outputs held as
// 6 packed-pair f32x2 accumulators x 4 y + 4 scalars (13th co).
// Grid (44 z, 11 y-tiles, 8 batch) = 3872 blocks.
//
// Per ci: cp.async-stage 5x8x48 input slab (7.7 KB) + [125][64] weight slab
// (32 KB), then 125 taps x (3 LDS.128 + 5 LDS + 4 packs + 28 FMA-pipe ops).
// ---------------------------------------------------------------------------
__global__ void __launch_bounds__(176) conv3d_kernel(
    const float* __restrict__ x, float* __restrict__ out)
{
    __shared__ __align__(16) float in_s[SS][NPY + SS - 1][DIN];  // 5x8x48
    __shared__ __align__(16) float w_s[TAPS * WPAD];             // 125x64 = 32 KB

    const int tx  = threadIdx.x;            // 0..43
    const int ty  = threadIdx.y;            // 0..3
    const int tid = ty * 44 + tx;           // 0..175
    const int zo  = blockIdx.x;             // 0..43
    const int yt  = blockIdx.y;             // 0..10
    const int n   = blockIdx.z;             // 0..7

    unsigned long long accp[6][NPY];        // packed pairs: co = ty*13 + 2*pp, +1
    float accs[NPY];                        // scalar: co = ty*13 + 12
    #pragma unroll
    for (int c = 0; c < 6; c++)
        #pragma unroll
        for (int p = 0; p < NPY; p++) accp[c][p] = 0ull;
    #pragma unroll
    for (int p = 0; p < NPY; p++) accs[p] = 0.f;

    const float* xn = x + (n * NCH) * (DIN * DIN * DIN);
    const uint32_t w_base  = (uint32_t)__cvta_generic_to_shared(w_s);
    const uint32_t in_base = (uint32_t)__cvta_generic_to_shared(in_s);

    #pragma unroll 1
    for (int ci = 0; ci < NCH; ci++) {
        __syncthreads();   // previous iteration's readers done before overwrite

        // --- stage input slab: z in [zo,zo+5), y in [4yt,4yt+8), full x ---
        const float* xc = xn + ci * (DIN * DIN * DIN);
        for (int t = tid; t < 480; t += 176) {       // 480 x 16B
            int x4  = (t % 12) * 4;
            int row = t / 12;                        // 0..39
            int zz  = row >> 3, yy = row & 7;
            uint32_t dst = in_base + (uint32_t)((((zz * 8) + yy) * DIN + x4) * 4);
            CP_ASYNC16(dst, xc + ((zo + zz) * DIN + (yt * NPY + yy)) * DIN + x4);
        }
        // --- stage weight slab for this ci (contiguous 16B chunks) ---
        const float* wg = g_kernel + ci * (TAPS * WPAD);
        for (int t = tid; t < (TAPS * WPAD) / 4; t += 176)   // 2000 x 16B
            CP_ASYNC16(w_base + (uint32_t)(t * 16), wg + t * 4);

        asm volatile("cp.async.commit_group;");
        asm volatile("cp.async.wait_group 0;" ::: "memory");
        __syncthreads();

        // --- compute: dz, dy real loops (I$ friendly), dx unrolled ---
        #pragma unroll 1
        for (int dz = 0; dz < SS; dz++) {
            #pragma unroll 1
            for (int dy = 0; dy < SS; dy++) {
                const float* ip = &in_s[dz][dy][tx];
                const int woff_f = (dz * SS + dy) * SS * WPAD + ty * 16;
                const uint32_t wrow_a = w_base + (uint32_t)(woff_f * 4);
                const float* wrow = &w_s[woff_f];
                #pragma unroll
                for (int dx = 0; dx < SS; dx++) {
                    float v0 = ip[dx];
                    float v1 = ip[DIN + dx];
                    float v2 = ip[2 * DIN + dx];
                    float v3 = ip[3 * DIN + dx];

                    // broadcast-pack v into f32x2 lanes
                    unsigned long long vp[NPY];
                    asm("mov.b64 %0, {%1, %1};" : "=l"(vp[0]) : "f"(v0));
                    asm("mov.b64 %0, {%1, %1};" : "=l"(vp[1]) : "f"(v1));
                    asm("mov.b64 %0, {%1, %1};" : "=l"(vp[2]) : "f"(v2));
                    asm("mov.b64 %0, {%1, %1};" : "=l"(vp[3]) : "f"(v3));

                    // 12 weights as 6 pre-packed f32x2 pairs (3x LDS.128)
                    uint32_t wa = wrow_a + (uint32_t)(dx * WPAD * 4);
                    unsigned long long wq[6];
                    asm volatile("ld.shared.v2.u64 {%0, %1}, [%2];"
                                 : "=l"(wq[0]), "=l"(wq[1]) : "r"(wa));
                    asm volatile("ld.shared.v2.u64 {%0, %1}, [%2+16];"
                                 : "=l"(wq[2]), "=l"(wq[3]) : "r"(wa));
                    asm volatile("ld.shared.v2.u64 {%0, %1}, [%2+32];"
                                 : "=l"(wq[4]), "=l"(wq[5]) : "r"(wa));
                    float w12 = wrow[dx * WPAD + 12];

                    #pragma unroll
                    for (int pp = 0; pp < 6; pp++) {
                        FMA2(accp[pp][0], wq[pp], vp[0]);
                        FMA2(accp[pp][1], wq[pp], vp[1]);
                        FMA2(accp[pp][2], wq[pp], vp[2]);
                        FMA2(accp[pp][3], wq[pp], vp[3]);
                    }
                    accs[0] = fmaf(w12, v0, accs[0]);
                    accs[1] = fmaf(w12, v1, accs[1]);
                    accs[2] = fmaf(w12, v2, accs[2]);
                    accs[3] = fmaf(w12, v3, accs[3]);
                }
            }
        }
    }

    // --- epilogue: unpack pairs, coalesced over tx ---
    float* on = out + (n * NCH) * (DOUT * DOUT * DOUT);
    #pragma unroll
    for (int pp = 0; pp < 6; pp++) {
        int co0 = ty * CPG + 2 * pp;       // low lane
        float* op0 = on + (co0 * DOUT + zo) * (DOUT * DOUT) + (yt * NPY) * DOUT + tx;
        float* op1 = op0 + DOUT * DOUT * DOUT;   // co0+1
        #pragma unroll
        for (int p = 0; p < NPY; p++) {
            float lo, hi;
            asm("mov.b64 {%0, %1}, %2;" : "=f"(lo), "=f"(hi) : "l"(accp[pp][p]));
            op0[p * DOUT] = lo;
            op1[p * DOUT] = hi;
        }
    }
    {
        int co = ty * CPG + 12;
        float* op = on + (co * DOUT + zo) * (DOUT * DOUT) + (yt * NPY) * DOUT + tx;
        #pragma unroll
        for (int p = 0; p < NPY; p++)
            op[p * DOUT] = accs[p];
    }
}

// ---------------------------------------------------------------------------
extern "C" void kernel_launch(void* const* d_in, const int* in_sizes, int n_in,
                              void* d_out, int out_size)
{
    const float* x = (const float*)d_in[0];
    const float* w = (const float*)d_in[1];

    build_filter_kernel<<<(NCH * TAPS * WPAD + 255) / 256, 256>>>(
        w,
        (const float*)d_in[2], (const float*)d_in[3], (const float*)d_in[4],
        (const float*)d_in[5], (const float*)d_in[6], (const float*)d_in[7],
        (const float*)d_in[8], (const float*)d_in[9], (const float*)d_in[10]);

    dim3 grid(DOUT, DOUT / NPY, 8);   // (44, 11, 8)
    dim3 block(44, 4);
    conv3d_kernel<<<grid, block>>>(x, (float*)d_out);
}